// round 1
// baseline (speedup 1.0000x reference)
#include <cuda_runtime.h>
#include <math.h>

#define B   16
#define C   128
#define HH  128
#define WW  128
#define HW  (HH*WW)
#define KK  9

// Scratch (static __device__ arrays are allowed; runtime alloc is not)
__device__ float g_mid[(size_t)B*C*HW];   // depthwise output, 128 MB
__device__ float g_kern[B*C*KK];          // per-(b,c) 3x3 kernels
__device__ float g_att[B*C];              // CA attention
__device__ float g_wt[C*C];               // conv_w transposed: g_wt[k*C+o] = conv_w[o][k]

__device__ __forceinline__ float lrelu(float v) { return v > 0.f ? v : 0.1f*v; }

// ---------------------------------------------------------------------------
// Kernel 1: per-batch kernel-generating MLP + CA attention + weight transpose
// grid = B, block = 256
// ---------------------------------------------------------------------------
__global__ void prep_kernel(const float* __restrict__ deg,
                            const float* __restrict__ w1,
                            const float* __restrict__ w2,
                            const float* __restrict__ caw1,
                            const float* __restrict__ caw2,
                            const float* __restrict__ convw)
{
    const int b   = blockIdx.x;
    const int tid = threadIdx.x;

    __shared__ float sdeg[C];
    __shared__ float st[C];
    __shared__ float sr[16];

    if (tid < C) sdeg[tid] = deg[b*C + tid];
    __syncthreads();

    // t = lrelu(deg @ w1^T)   (w1 is (out,in) row-major)
    if (tid < C) {
        float acc = 0.f;
        const float* wrow = w1 + tid*C;
        #pragma unroll 4
        for (int c2 = 0; c2 < C; ++c2) acc += sdeg[c2]*wrow[c2];
        st[tid] = lrelu(acc);
    }
    // CA hidden: r = lrelu(deg @ ca_w1^T), 16 outputs
    if (tid >= 128 && tid < 144) {
        int r = tid - 128;
        float acc = 0.f;
        const float* wrow = caw1 + r*C;
        #pragma unroll 4
        for (int c2 = 0; c2 < C; ++c2) acc += sdeg[c2]*wrow[c2];
        sr[r] = lrelu(acc);
    }
    __syncthreads();

    // kern = t @ w2^T  -> (C*KK) values; layout j = c*9 + (kh*3+kw)
    for (int j = tid; j < C*KK; j += blockDim.x) {
        float acc = 0.f;
        const float* wrow = w2 + j*C;
        #pragma unroll 4
        for (int i = 0; i < C; ++i) acc += st[i]*wrow[i];
        g_kern[b*C*KK + j] = acc;
    }

    // att = sigmoid(r @ ca_w2^T)
    if (tid < C) {
        float acc = 0.f;
        const float* wrow = caw2 + tid*16;
        #pragma unroll
        for (int r = 0; r < 16; ++r) acc += sr[r]*wrow[r];
        g_att[b*C + tid] = 1.f/(1.f + expf(-acc));
    }

    // block 0: transpose conv_w for the GEMM (coalesced smem fills later)
    if (b == 0) {
        for (int idx = tid; idx < C*C; idx += blockDim.x) {
            int o = idx & (C-1);
            int k = idx >> 7;
            g_wt[idx] = convw[o*C + k];   // g_wt[k][o]
        }
    }
}

// ---------------------------------------------------------------------------
// Kernel 2: per-(b,c) dynamic depthwise 3x3 conv + lrelu
// grid = B*C (one 128x128 plane per block), block = 256
// Plane (64 KB) fits in L1, so the 9-tap reads are mostly L1 hits.
// ---------------------------------------------------------------------------
__global__ void dwconv_kernel(const float* __restrict__ x0)
{
    const int bc = blockIdx.x;                   // b*C + c
    const float* __restrict__ src = x0 + (size_t)bc*HW;
    float* __restrict__ dst = g_mid + (size_t)bc*HW;

    float k[9];
    #pragma unroll
    for (int i = 0; i < 9; ++i) k[i] = g_kern[bc*9 + i];

    for (int p = threadIdx.x; p < HW; p += blockDim.x) {
        const int h = p >> 7;
        const int w = p & (WW-1);
        float acc = 0.f;
        #pragma unroll
        for (int kh = 0; kh < 3; ++kh) {
            const int hh = h + kh - 1;
            if (hh < 0 || hh >= HH) continue;
            const float* row = src + hh*WW;
            #pragma unroll
            for (int kw = 0; kw < 3; ++kw) {
                const int ww2 = w + kw - 1;
                if (ww2 < 0 || ww2 >= WW) continue;
                acc += k[kh*3 + kw] * row[ww2];
            }
        }
        dst[p] = lrelu(acc);
    }
}

// ---------------------------------------------------------------------------
// Kernel 3: 1x1 conv as register-tiled SGEMM + fused bias + x0*att residual
// out[b,o,p] = sum_k W[o,k]*mid[b,k,p] + bias[o] + x0[b,o,p]*att[b,o]
// grid = (HW/128, B), block = 256 (16x16 threads, 8x8 micro-tile)
// ---------------------------------------------------------------------------
#define KC 32
__global__ void __launch_bounds__(256, 2)
gemm_kernel(const float* __restrict__ x0,
            const float* __restrict__ bias,
            float* __restrict__ out)
{
    __shared__ float sW[KC][C];       // sW[k][o]
    __shared__ float sM[KC][C + 4];   // sM[k][p], padded

    const int b    = blockIdx.y;
    const int pix0 = blockIdx.x * 128;
    const int tid  = threadIdx.x;
    const int ty   = tid >> 4;        // 0..15 -> out-channel group
    const int tx   = tid & 15;        // 0..15 -> pixel group
    const int o0   = ty * 8;
    const int p0   = tx * 8;

    float acc[8][8];
    #pragma unroll
    for (int i = 0; i < 8; ++i)
        #pragma unroll
        for (int j = 0; j < 8; ++j) acc[i][j] = 0.f;

    const float* __restrict__ midb = g_mid + (size_t)b*C*HW + pix0;

    for (int k0 = 0; k0 < C; k0 += KC) {
        // cooperative loads: both coalesced global, sequential smem
        #pragma unroll
        for (int idx = tid; idx < KC*C; idx += 256) {
            const int kk = idx >> 7;
            const int oo = idx & (C-1);
            sW[kk][oo] = g_wt[(k0 + kk)*C + oo];
            sM[kk][oo] = midb[(size_t)(k0 + kk)*HW + oo];
        }
        __syncthreads();

        #pragma unroll
        for (int kk = 0; kk < KC; ++kk) {
            float a[8], bb[8];
            #pragma unroll
            for (int i = 0; i < 8; ++i) a[i]  = sW[kk][o0 + i];
            #pragma unroll
            for (int j = 0; j < 8; ++j) bb[j] = sM[kk][p0 + j];
            #pragma unroll
            for (int i = 0; i < 8; ++i)
                #pragma unroll
                for (int j = 0; j < 8; ++j)
                    acc[i][j] += a[i]*bb[j];
        }
        __syncthreads();
    }

    // fused epilogue: bias + residual
    #pragma unroll
    for (int i = 0; i < 8; ++i) {
        const int o  = o0 + i;
        const float bo = bias[o];
        const float at = g_att[b*C + o];
        const float* __restrict__ xr  = x0  + ((size_t)(b*C + o))*HW + pix0 + p0;
        float* __restrict__       orow = out + ((size_t)(b*C + o))*HW + pix0 + p0;
        #pragma unroll
        for (int j = 0; j < 8; ++j)
            orow[j] = acc[i][j] + bo + xr[j]*at;
    }
}

// ---------------------------------------------------------------------------
extern "C" void kernel_launch(void* const* d_in, const int* in_sizes, int n_in,
                              void* d_out, int out_size)
{
    const float* x0    = (const float*)d_in[0];
    const float* deg   = (const float*)d_in[1];
    const float* w1    = (const float*)d_in[2];
    const float* w2    = (const float*)d_in[3];
    const float* convw = (const float*)d_in[4];
    const float* convb = (const float*)d_in[5];
    const float* caw1  = (const float*)d_in[6];
    const float* caw2  = (const float*)d_in[7];
    float* out = (float*)d_out;

    prep_kernel<<<B, 256>>>(deg, w1, w2, caw1, caw2, convw);
    dwconv_kernel<<<B*C, 256>>>(x0);
    gemm_kernel<<<dim3(HW/128, B), 256>>>(x0, convb, out);
}

// round 2
// speedup vs baseline: 2.6818x; 2.6818x over previous
#include <cuda_runtime.h>
#include <math.h>
#include <stdint.h>

#define B   16
#define C   128
#define HH  128
#define WW  128
#define HW  (HH*WW)
#define KK  9
#define KCH 32

// Scratch
__device__ float g_mid[(size_t)B*C*HW];   // depthwise output
__device__ float g_kern[B*C*KK];          // per-(b,c) 3x3 kernels
__device__ float g_att[B*C];              // CA attention
__device__ float g_t[B*C];                // hidden MLP activations

__device__ __forceinline__ float lrelu(float v) { return v > 0.f ? v : 0.1f*v; }

__device__ __forceinline__ float to_tf32(float x) {
    uint32_t u;
    asm("cvt.rna.tf32.f32 %0, %1;" : "=r"(u) : "f"(x));
    return __uint_as_float(u);
}

__device__ __forceinline__ void mma_tf32(float* d, const uint32_t* a, const uint32_t* bf) {
    asm volatile(
        "mma.sync.aligned.m16n8k8.row.col.f32.tf32.tf32.f32 "
        "{%0,%1,%2,%3}, {%4,%5,%6,%7}, {%8,%9}, {%0,%1,%2,%3};"
        : "+f"(d[0]), "+f"(d[1]), "+f"(d[2]), "+f"(d[3])
        : "r"(a[0]), "r"(a[1]), "r"(a[2]), "r"(a[3]), "r"(bf[0]), "r"(bf[1]));
}

// ---------------------------------------------------------------------------
// P1: per-batch MLP hidden layer + CA attention. grid=B, block=256.
// ---------------------------------------------------------------------------
__global__ void prep1_kernel(const float* __restrict__ deg,
                             const float* __restrict__ w1,
                             const float* __restrict__ caw1,
                             const float* __restrict__ caw2)
{
    const int b   = blockIdx.x;
    const int tid = threadIdx.x;

    __shared__ float sdeg[C];
    __shared__ float sr[16];

    if (tid < C) sdeg[tid] = deg[b*C + tid];
    __syncthreads();

    if (tid < C) {
        float acc = 0.f;
        const float* wrow = w1 + tid*C;
        #pragma unroll 8
        for (int c2 = 0; c2 < C; ++c2) acc += sdeg[c2]*wrow[c2];
        g_t[b*C + tid] = lrelu(acc);
    }
    if (tid >= 128 && tid < 144) {
        int r = tid - 128;
        float acc = 0.f;
        const float* wrow = caw1 + r*C;
        #pragma unroll 8
        for (int c2 = 0; c2 < C; ++c2) acc += sdeg[c2]*wrow[c2];
        sr[r] = lrelu(acc);
    }
    __syncthreads();

    if (tid < C) {
        float acc = 0.f;
        const float* wrow = caw2 + tid*16;
        #pragma unroll
        for (int r = 0; r < 16; ++r) acc += sr[r]*wrow[r];
        g_att[b*C + tid] = 1.f/(1.f + expf(-acc));
    }
}

// ---------------------------------------------------------------------------
// P2: kernel coefficients, one warp per output. outputs = B*C*KK = 18432.
// grid = 18432/8 = 2304 blocks, block = 256 (8 warps).
// ---------------------------------------------------------------------------
__global__ void prep2_kernel(const float* __restrict__ w2)
{
    const int wid  = threadIdx.x >> 5;
    const int lane = threadIdx.x & 31;
    const int j    = blockIdx.x*8 + wid;       // global output index
    const int b    = j / (C*KK);
    const int j2   = j - b*(C*KK);             // row of w2

    const float* trow = g_t + b*C;
    const float* wrow = w2 + (size_t)j2*C;

    float acc = 0.f;
    #pragma unroll
    for (int i = 0; i < 4; ++i) {
        const int idx = lane*4 + i;
        acc += trow[idx]*wrow[idx];
    }
    #pragma unroll
    for (int s = 16; s > 0; s >>= 1) acc += __shfl_xor_sync(0xffffffffu, acc, s);
    if (lane == 0) g_kern[(size_t)b*C*KK + j2] = acc;
}

// ---------------------------------------------------------------------------
// dwconv: per-(b,c) dynamic 3x3 depthwise conv + lrelu, 4 px/thread, float4.
// grid = B*C, block = 256.
// ---------------------------------------------------------------------------
__global__ void dwconv_kernel(const float* __restrict__ x0)
{
    const int bc = blockIdx.x;
    const float* __restrict__ src = x0 + (size_t)bc*HW;
    float* __restrict__ dst = g_mid + (size_t)bc*HW;

    float k[9];
    #pragma unroll
    for (int i = 0; i < 9; ++i) k[i] = g_kern[bc*9 + i];

    for (int p4 = threadIdx.x*4; p4 < HW; p4 += blockDim.x*4) {
        const int h  = p4 >> 7;
        const int w0 = p4 & (WW-1);
        float acc0 = 0.f, acc1 = 0.f, acc2 = 0.f, acc3 = 0.f;

        #pragma unroll
        for (int kh = 0; kh < 3; ++kh) {
            const int hh = h + kh - 1;
            if (hh < 0 || hh >= HH) continue;
            const float* row = src + hh*WW;
            float4 cv = *(const float4*)(row + w0);
            float vl = (w0 > 0)      ? row[w0-1] : 0.f;
            float vr = (w0 < WW-4)   ? row[w0+4] : 0.f;
            const float k0 = k[kh*3+0], k1 = k[kh*3+1], k2 = k[kh*3+2];
            acc0 += k0*vl   + k1*cv.x + k2*cv.y;
            acc1 += k0*cv.x + k1*cv.y + k2*cv.z;
            acc2 += k0*cv.y + k1*cv.z + k2*cv.w;
            acc3 += k0*cv.z + k1*cv.w + k2*vr;
        }
        float4 o;
        o.x = lrelu(acc0); o.y = lrelu(acc1); o.z = lrelu(acc2); o.w = lrelu(acc3);
        *(float4*)(dst + p4) = o;
    }
}

// ---------------------------------------------------------------------------
// GEMM (TF32 tensor cores): out[b,o,p] = sum_k W[o,k]*mid[b,k,p] + bias[o]
//                                        + x0[b,o,p]*att[b,o]
// Block tile M=128(o) x N=128(p), K chunks of 32. 8 warps, each 64x32.
// grid = (HW/128, B), block = 256.
// ---------------------------------------------------------------------------
__global__ void __launch_bounds__(256, 2)
gemm_tf32(const float* __restrict__ convw,
          const float* __restrict__ bias,
          const float* __restrict__ x0,
          float* __restrict__ out)
{
    __shared__ float sA[C*36];        // [o][36]  (32 k-values + pad)
    __shared__ float sB[KCH*136];     // [k][136] (128 pixels + pad)

    const int b    = blockIdx.y;
    const int pix0 = blockIdx.x * 128;
    const int tid  = threadIdx.x;
    const int wid  = tid >> 5;
    const int lane = tid & 31;
    const int g    = lane >> 2;       // group id 0..7
    const int tg   = lane & 3;        // thread-in-group 0..3
    const int wm0  = (wid >> 2) * 64; // warp m origin
    const int wn0  = (wid & 3) * 32;  // warp n origin

    float d[4][4][4];
    #pragma unroll
    for (int mt = 0; mt < 4; ++mt)
        #pragma unroll
        for (int nt = 0; nt < 4; ++nt)
            #pragma unroll
            for (int r = 0; r < 4; ++r) d[mt][nt][r] = 0.f;

    const float* __restrict__ midb = g_mid + (size_t)b*C*HW + pix0;

    for (int kc = 0; kc < C; kc += KCH) {
        // --- load A chunk: W[o, kc..kc+31], tf32-converted ---
        #pragma unroll
        for (int i = tid; i < C*KCH/4; i += 256) {
            const int o  = i >> 3;
            const int k4 = (i & 7) * 4;
            float4 v = *(const float4*)(convw + o*C + kc + k4);
            float* s = sA + o*36 + k4;
            s[0] = to_tf32(v.x); s[1] = to_tf32(v.y);
            s[2] = to_tf32(v.z); s[3] = to_tf32(v.w);
        }
        // --- load B chunk: mid[kc..kc+31, pix0..pix0+127], tf32-converted ---
        #pragma unroll
        for (int i = tid; i < KCH*128/4; i += 256) {
            const int kk = i >> 5;
            const int p4 = (i & 31) * 4;
            float4 v = *(const float4*)(midb + (size_t)(kc + kk)*HW + p4);
            float* s = sB + kk*136 + p4;
            s[0] = to_tf32(v.x); s[1] = to_tf32(v.y);
            s[2] = to_tf32(v.z); s[3] = to_tf32(v.w);
        }
        __syncthreads();

        #pragma unroll
        for (int ks = 0; ks < KCH; ks += 8) {
            uint32_t a[4][4];
            #pragma unroll
            for (int mt = 0; mt < 4; ++mt) {
                const int o = wm0 + mt*16;
                a[mt][0] = __float_as_uint(sA[(o+g  )*36 + ks + tg    ]);
                a[mt][1] = __float_as_uint(sA[(o+g+8)*36 + ks + tg    ]);
                a[mt][2] = __float_as_uint(sA[(o+g  )*36 + ks + tg + 4]);
                a[mt][3] = __float_as_uint(sA[(o+g+8)*36 + ks + tg + 4]);
            }
            uint32_t bf[4][2];
            #pragma unroll
            for (int nt = 0; nt < 4; ++nt) {
                const int p = wn0 + nt*8 + g;
                bf[nt][0] = __float_as_uint(sB[(ks + tg    )*136 + p]);
                bf[nt][1] = __float_as_uint(sB[(ks + tg + 4)*136 + p]);
            }
            #pragma unroll
            for (int mt = 0; mt < 4; ++mt)
                #pragma unroll
                for (int nt = 0; nt < 4; ++nt)
                    mma_tf32(d[mt][nt], a[mt], bf[nt]);
        }
        __syncthreads();
    }

    // --- fused epilogue: bias + x0*att residual ---
    #pragma unroll
    for (int mt = 0; mt < 4; ++mt) {
        #pragma unroll
        for (int half = 0; half < 2; ++half) {
            const int o  = wm0 + mt*16 + g + half*8;
            const float bo = bias[o];
            const float at = g_att[b*C + o];
            const float* __restrict__ xrow = x0  + ((size_t)(b*C + o))*HW + pix0;
            float* __restrict__       orow = out + ((size_t)(b*C + o))*HW + pix0;
            #pragma unroll
            for (int nt = 0; nt < 4; ++nt) {
                const int cc = wn0 + nt*8 + 2*tg;
                float2 xv = *(const float2*)(xrow + cc);
                float2 ov;
                ov.x = d[mt][nt][half*2 + 0] + bo + xv.x*at;
                ov.y = d[mt][nt][half*2 + 1] + bo + xv.y*at;
                *(float2*)(orow + cc) = ov;
            }
        }
    }
}

// ---------------------------------------------------------------------------
extern "C" void kernel_launch(void* const* d_in, const int* in_sizes, int n_in,
                              void* d_out, int out_size)
{
    const float* x0    = (const float*)d_in[0];
    const float* deg   = (const float*)d_in[1];
    const float* w1    = (const float*)d_in[2];
    const float* w2    = (const float*)d_in[3];
    const float* convw = (const float*)d_in[4];
    const float* convb = (const float*)d_in[5];
    const float* caw1  = (const float*)d_in[6];
    const float* caw2  = (const float*)d_in[7];
    float* out = (float*)d_out;

    prep1_kernel<<<B, 256>>>(deg, w1, caw1, caw2);
    prep2_kernel<<<(B*C*KK)/8, 256>>>(w2);
    dwconv_kernel<<<B*C, 256>>>(x0);
    gemm_tf32<<<dim3(HW/128, B), 256>>>(convw, convb, x0, out);
}